// round 1
// baseline (speedup 1.0000x reference)
#include <cuda_runtime.h>
#include <math_constants.h>

// Problem constants (from reference)
#define B_      256
#define N_      16
#define M_      128
#define V_      64
#define H_      256
#define K_      8
#define NP1_    17      // N + 1
#define KO_     136     // K * (N+1)
#define TYPES_  12
#define NTHREADS 512

// Output layout: new_d [B,M,V] = 2,097,152 floats, then new_v [B,40,3,V] = 1,966,080 zeros
#define OUT_D_ELEMS ((size_t)B_ * M_ * V_)
#define OUT_V_PER_B (40 * 3 * V_)   // 7680 floats per batch

__global__ __launch_bounds__(NTHREADS, 2)
void fused_dt_apply_kernel(
    const float* __restrict__ decodings,     // [B,N,M,V]
    const int*   __restrict__ target_types,  // [B]
    const int*   __restrict__ spans,         // [B]
    const float* __restrict__ te_table,      // [21,H]
    const float* __restrict__ W_sem,         // [15,12,H,KO]
    const float* __restrict__ b_sem,         // [15,12,KO]
    const float* __restrict__ gumbel,        // [B,K,NP1]
    float*       __restrict__ out)           // [OUT_D | OUT_V]
{
    __shared__ float  s_tile[M_ * V_];   // 32 KB staging for one decoding tile
    __shared__ float  s_te[H_];
    __shared__ double s_partd[2 * KO_];
    __shared__ float  s_logit[KO_];
    __shared__ int    s_sel[K_];
    __shared__ int    s_red[16];
    __shared__ int    s_olen;

    const int b   = blockIdx.x;
    const int tid = threadIdx.x;
    const int tt  = target_types[b];
    const int sp  = spans[b];

    // ---------------- Phase 1: selection indices sel[k] in [0,16] ----------------
    if (tt == 20) {
        // fixed start template: k=0 -> decoding 0 (n=1), others -> pad (n=0)
        if (tid < K_) s_sel[tid] = (tid == 0) ? 1 : 0;
        __syncthreads();
    } else {
        if (tid < H_) s_te[tid] = te_table[(size_t)tt * H_ + tid];
        __syncthreads();

        const size_t gidx = (size_t)(sp - 2) * TYPES_ + (size_t)(tt - 9);
        const float* __restrict__ Wg = W_sem + gidx * (size_t)H_ * KO_;
        const float* __restrict__ bg = b_sem + gidx * KO_;

        // 272 threads: (half of H) x (136 outputs). 8 fp32 accumulators each,
        // combined in fp64 to keep logit error ~1e-7 (matches reference's own noise).
        if (tid < 2 * KO_) {
            const int o  = (tid < KO_) ? tid : (tid - KO_);
            const int h0 = (tid < KO_) ? 0 : 128;
            float a0 = 0.f, a1 = 0.f, a2 = 0.f, a3 = 0.f;
            float a4 = 0.f, a5 = 0.f, a6 = 0.f, a7 = 0.f;
            const float* wp = Wg + (size_t)h0 * KO_ + o;
            const float* tp = s_te + h0;
            #pragma unroll 4
            for (int h = 0; h < 128; h += 8) {
                a0 = fmaf(tp[h + 0], wp[(size_t)(h + 0) * KO_], a0);
                a1 = fmaf(tp[h + 1], wp[(size_t)(h + 1) * KO_], a1);
                a2 = fmaf(tp[h + 2], wp[(size_t)(h + 2) * KO_], a2);
                a3 = fmaf(tp[h + 3], wp[(size_t)(h + 3) * KO_], a3);
                a4 = fmaf(tp[h + 4], wp[(size_t)(h + 4) * KO_], a4);
                a5 = fmaf(tp[h + 5], wp[(size_t)(h + 5) * KO_], a5);
                a6 = fmaf(tp[h + 6], wp[(size_t)(h + 6) * KO_], a6);
                a7 = fmaf(tp[h + 7], wp[(size_t)(h + 7) * KO_], a7);
            }
            double sum = (((double)a0 + (double)a1) + ((double)a2 + (double)a3))
                       + (((double)a4 + (double)a5) + ((double)a6 + (double)a7));
            s_partd[tid] = sum;
        }
        __syncthreads();

        if (tid < KO_) {
            s_logit[tid] = (float)(s_partd[tid] + s_partd[tid + KO_]) + bg[tid];
        }
        __syncthreads();

        // argmax over valid n of (logits + gumbel): warp w handles k = w
        const int w    = tid >> 5;
        const int lane = tid & 31;
        if (w < K_) {
            int   n   = lane;
            float val = -CUDART_INF_F;
            if (n < NP1_ && n <= sp) {
                val = s_logit[w * NP1_ + n]
                    + gumbel[((size_t)b * K_ + w) * NP1_ + n];
            }
            float bv = val;
            int   bn = n;
            #pragma unroll
            for (int off = 16; off; off >>= 1) {
                float ov = __shfl_down_sync(0xffffffffu, bv, off);
                int   on = __shfl_down_sync(0xffffffffu, bn, off);
                if (ov > bv || (ov == bv && on < bn)) { bv = ov; bn = on; }
            }
            if (lane == 0) s_sel[w] = bn;
        }
        __syncthreads();
    }

    // ---------------- Phase 2: sequential template application ----------------
    int idx = 0;
    for (int k = 0; k < K_; k++) {
        const int n = s_sel[k];
        if (n == 0) continue;       // pad template: contributes nothing
        if (idx >= M_) break;       // output full: remaining segments truncated to 0

        const float* __restrict__ tile =
            decodings + ((size_t)b * N_ + (size_t)(n - 1)) * (M_ * V_);

        // stage tile into SMEM (coalesced float4)
        #pragma unroll
        for (int i = tid; i < (M_ * V_) / 4; i += NTHREADS)
            ((float4*)s_tile)[i] = ((const float4*)tile)[i];
        __syncthreads();

        // olen_raw = 1 + last row j where exists v>0 with d[j][v] > d[j][0]
        const int w    = tid >> 5;
        const int lane = tid & 31;
        int local = 0;
        #pragma unroll
        for (int r = 0; r < 8; r++) {
            const int j = w * 8 + r;
            float a = s_tile[j * V_ + lane];
            float c = s_tile[j * V_ + lane + 32];
            float m = (lane == 0) ? c : fmaxf(a, c);   // exclude v=0 from the max
            #pragma unroll
            for (int off = 16; off; off >>= 1)
                m = fmaxf(m, __shfl_down_sync(0xffffffffu, m, off));
            float d0 = __shfl_sync(0xffffffffu, a, 0);
            m        = __shfl_sync(0xffffffffu, m, 0);
            if (m > d0) local = j + 1;
        }
        if (lane == 0) s_red[w] = local;
        __syncthreads();
        if (tid == 0) {
            int o = 0;
            #pragma unroll
            for (int i = 0; i < 16; i++) o = max(o, s_red[i]);
            s_olen = min(o, M_ - idx);
        }
        __syncthreads();
        const int olen = s_olen;

        // copy rows [0, olen) to output at row offset idx
        float* __restrict__ dst = out + ((size_t)b * M_ + idx) * V_;
        const int n4 = olen * (V_ / 4);
        for (int i = tid; i < n4; i += NTHREADS)
            ((float4*)dst)[i] = ((const float4*)s_tile)[i];

        idx += olen;
        __syncthreads();   // protect s_tile before next iteration's reload
    }

    // ---------------- Phase 3: zero fill (tail of new_d, all of new_v) ----------------
    const float4 z = make_float4(0.f, 0.f, 0.f, 0.f);
    {
        float* __restrict__ dst = out + ((size_t)b * M_ + idx) * V_;
        const int rem4 = (M_ - idx) * (V_ / 4);
        for (int i = tid; i < rem4; i += NTHREADS)
            ((float4*)dst)[i] = z;
    }
    {
        float* __restrict__ dv = out + OUT_D_ELEMS + (size_t)b * OUT_V_PER_B;
        for (int i = tid; i < OUT_V_PER_B / 4; i += NTHREADS)
            ((float4*)dv)[i] = z;
    }
}

extern "C" void kernel_launch(void* const* d_in, const int* in_sizes, int n_in,
                              void* d_out, int out_size)
{
    (void)in_sizes; (void)n_in; (void)out_size;
    const float* decodings    = (const float*)d_in[0];
    // d_in[1] = variables : unused (new_v is all zeros)
    const int*   target_types = (const int*)d_in[2];
    const int*   spans        = (const int*)d_in[3];
    const float* te_table     = (const float*)d_in[4];
    const float* W_sem        = (const float*)d_in[5];
    const float* b_sem        = (const float*)d_in[6];
    const float* gumbel       = (const float*)d_in[7];
    float*       out          = (float*)d_out;

    fused_dt_apply_kernel<<<B_, NTHREADS>>>(
        decodings, target_types, spans, te_table, W_sem, b_sem, gumbel, out);
}